// round 1
// baseline (speedup 1.0000x reference)
#include <cuda_runtime.h>
#include <cuda_bf16.h>
#include <cstdint>

#define Bn 64
#define Qn 2048
#define Kdim 2048
#define Dn 128
#define QT 16
#define CK 64

#define SROW 2052      /* floats per S row   (pad: 2052 mod 32 = 4)        */
#define QROW 136       /* bf16 per Q row     (pad: 136/2 mod 32 = 4? see KROW note) */
#define KROW 136       /* bf16 per K row  -> half-elem shift 68 mod 32 = 4, banks 4g+ct... use 8 via /2: elem/2 shift = 68 -> 4 */
#define VPROW 136      /* u32 per V pair row (136 mod 32 = 8 -> banks 8*ct+g bijection) */

#define OFF_S    0
#define SZ_S     (QT*SROW*4)           /* 131328 */
#define OFF_QH   (OFF_S + SZ_S)
#define SZ_Q     (QT*QROW*2)           /* 4352 */
#define OFF_QL   (OFF_QH + SZ_Q)
#define OFF_KH   (OFF_QL + SZ_Q)       /* K stage (bf16) aliases V stage (u32) */
#define SZ_KV    (CK*KROW*2)           /* 17408 ; V packed: 32*136*4 = 17408 */
#define OFF_KL   (OFF_KH + SZ_KV)
#define SMEM_TOTAL (OFF_KL + SZ_KV)    /* 174848 bytes */

#define MMA_BF16(C, a0, a1, a2, a3, b0, b1)                                   \
  asm volatile(                                                               \
      "mma.sync.aligned.m16n8k16.row.col.f32.bf16.bf16.f32 "                  \
      "{%0,%1,%2,%3}, {%4,%5,%6,%7}, {%8,%9}, {%0,%1,%2,%3};\n"               \
      : "+f"(C[0]), "+f"(C[1]), "+f"(C[2]), "+f"(C[3])                        \
      : "r"(a0), "r"(a1), "r"(a2), "r"(a3), "r"(b0), "r"(b1))

// Split two fp32 into (hi, lo) bf16x2 packs: x = hi + lo to ~2^-18 relative.
__device__ __forceinline__ void splitpack(float x, float y, uint32_t& h, uint32_t& l) {
    __nv_bfloat162 hh = __floats2bfloat162_rn(x, y);
    float hx = __low2float(hh);
    float hy = __high2float(hh);
    __nv_bfloat162 ll = __floats2bfloat162_rn(x - hx, y - hy);
    h = *reinterpret_cast<uint32_t*>(&hh);
    l = *reinterpret_cast<uint32_t*>(&ll);
}

__global__ void __launch_bounds__(256, 1)
attn_fused_kernel(const float* __restrict__ qg, const float* __restrict__ kg,
                  const float* __restrict__ vg, const int* __restrict__ vlg,
                  float* __restrict__ outg, float* __restrict__ attng)
{
    extern __shared__ unsigned char smem[];
    float*          sS  = (float*)(smem + OFF_S);
    __nv_bfloat16*  sQh = (__nv_bfloat16*)(smem + OFF_QH);
    __nv_bfloat16*  sQl = (__nv_bfloat16*)(smem + OFF_QL);
    __nv_bfloat16*  sKh = (__nv_bfloat16*)(smem + OFF_KH);
    __nv_bfloat16*  sKl = (__nv_bfloat16*)(smem + OFF_KL);
    uint32_t*       sVh = (uint32_t*)(smem + OFF_KH);
    uint32_t*       sVl = (uint32_t*)(smem + OFF_KL);

    const int b    = blockIdx.y;
    const int q0   = blockIdx.x * QT;
    const int tid  = threadIdx.x;
    const int w    = tid >> 5;
    const int lane = tid & 31;
    const int g    = lane >> 2;   // groupID
    const int ct   = lane & 3;    // thread-in-group
    const int VL   = vlg[b];

    const float* qp = qg + ((size_t)b * Qn + q0) * Dn;
    const float* kp = kg + (size_t)b * Kdim * Dn;
    const float* vp = vg + (size_t)b * Kdim * Dn;

    // ---------------- stage Q tile (16x128) as hi/lo bf16 ----------------
    for (int i = tid; i < QT * Dn / 4; i += 256) {
        int r = i >> 5;             // (i*4)/128
        int c = (i & 31) << 2;
        float4 x = *(const float4*)(qp + r * Dn + c);
        uint32_t h0, l0, h1, l1;
        splitpack(x.x, x.y, h0, l0);
        splitpack(x.z, x.w, h1, l1);
        *(uint32_t*)(sQh + r * QROW + c)     = h0;
        *(uint32_t*)(sQh + r * QROW + c + 2) = h1;
        *(uint32_t*)(sQl + r * QROW + c)     = l0;
        *(uint32_t*)(sQl + r * QROW + c + 2) = l1;
    }
    __syncthreads();

    // Q fragments live in registers for the whole score phase (8 ksteps x 4 regs x hi/lo)
    uint32_t aQh[8][4], aQl[8][4];
#pragma unroll
    for (int kk = 0; kk < 8; kk++) {
        int d0 = kk * 16 + 2 * ct;
        aQh[kk][0] = *(const uint32_t*)(sQh + g * QROW + d0);
        aQh[kk][1] = *(const uint32_t*)(sQh + (g + 8) * QROW + d0);
        aQh[kk][2] = *(const uint32_t*)(sQh + g * QROW + d0 + 8);
        aQh[kk][3] = *(const uint32_t*)(sQh + (g + 8) * QROW + d0 + 8);
        aQl[kk][0] = *(const uint32_t*)(sQl + g * QROW + d0);
        aQl[kk][1] = *(const uint32_t*)(sQl + (g + 8) * QROW + d0);
        aQl[kk][2] = *(const uint32_t*)(sQl + g * QROW + d0 + 8);
        aQl[kk][3] = *(const uint32_t*)(sQl + (g + 8) * QROW + d0 + 8);
    }

    // ---------------- score phase: S = Q K^T / sqrt(D) ----------------
    const int kb = w * 8;   // warp's key offset within chunk
    for (int c0 = 0; c0 < Kdim; c0 += CK) {
        __syncthreads();    // previous chunk fully consumed
#pragma unroll
        for (int i = 0; i < 8; i++) {
            int idx = tid + i * 256;       // float4 index over 64x128 chunk
            int r = idx >> 5;
            int c = (idx & 31) << 2;
            float4 x = *(const float4*)(kp + (size_t)(c0 + r) * Dn + c);
            uint32_t h0, l0, h1, l1;
            splitpack(x.x, x.y, h0, l0);
            splitpack(x.z, x.w, h1, l1);
            *(uint32_t*)(sKh + r * KROW + c)     = h0;
            *(uint32_t*)(sKh + r * KROW + c + 2) = h1;
            *(uint32_t*)(sKl + r * KROW + c)     = l0;
            *(uint32_t*)(sKl + r * KROW + c + 2) = l1;
        }
        __syncthreads();

        float cA[4] = {0.f, 0.f, 0.f, 0.f};
        float cB[4] = {0.f, 0.f, 0.f, 0.f};
        float cC[4] = {0.f, 0.f, 0.f, 0.f};
#pragma unroll
        for (int kk = 0; kk < 8; kk++) {
            const __nv_bfloat16* kh = sKh + (kb + g) * KROW + kk * 16 + 2 * ct;
            const __nv_bfloat16* kl = sKl + (kb + g) * KROW + kk * 16 + 2 * ct;
            uint32_t bh0 = *(const uint32_t*)kh;
            uint32_t bh1 = *(const uint32_t*)(kh + 8);
            uint32_t bl0 = *(const uint32_t*)kl;
            uint32_t bl1 = *(const uint32_t*)(kl + 8);
            MMA_BF16(cA, aQh[kk][0], aQh[kk][1], aQh[kk][2], aQh[kk][3], bh0, bh1);
            MMA_BF16(cB, aQh[kk][0], aQh[kk][1], aQh[kk][2], aQh[kk][3], bl0, bl1);
            MMA_BF16(cC, aQl[kk][0], aQl[kk][1], aQl[kk][2], aQl[kk][3], bh0, bh1);
        }
        const float scale = 0.08838834764831845f;   // 1/sqrt(128)
        int col = c0 + kb + 2 * ct;
        sS[g * SROW + col]           = (cA[0] + cB[0] + cC[0]) * scale;
        sS[g * SROW + col + 1]       = (cA[1] + cB[1] + cC[1]) * scale;
        sS[(g + 8) * SROW + col]     = (cA[2] + cB[2] + cC[2]) * scale;
        sS[(g + 8) * SROW + col + 1] = (cA[3] + cB[3] + cC[3]) * scale;
    }
    __syncthreads();

    // ---------------- softmax (masked) + attn writeback ----------------
#pragma unroll
    for (int rr = 0; rr < 2; rr++) {
        int r = w * 2 + rr;
        float* Srow = sS + r * SROW;
        float mx = -3.402823466e38f;
        for (int j = lane; j < Kdim; j += 32) {
            float vv = (j < VL) ? Srow[j] : -1e9f;
            mx = fmaxf(mx, vv);
        }
#pragma unroll
        for (int o = 16; o > 0; o >>= 1)
            mx = fmaxf(mx, __shfl_xor_sync(0xffffffffu, mx, o));
        float sum = 0.f;
        for (int j = lane; j < Kdim; j += 32) {
            float vv = (j < VL) ? Srow[j] : -1e9f;
            float e = __expf(vv - mx);
            Srow[j] = e;
            sum += e;
        }
#pragma unroll
        for (int o = 16; o > 0; o >>= 1)
            sum += __shfl_xor_sync(0xffffffffu, sum, o);
        float inv = 1.f / sum;
        float* arow = attng + ((size_t)b * Qn + q0 + r) * Kdim;
        for (int j = lane * 4; j < Kdim; j += 128) {
            float4 e = *(float4*)(Srow + j);
            e.x *= inv; e.y *= inv; e.z *= inv; e.w *= inv;
            *(float4*)(Srow + j) = e;
            *(float4*)(arow + j) = e;
        }
    }

    // ---------------- PV phase: out = P V ----------------
    float oA[2][4] = {{0.f,0.f,0.f,0.f},{0.f,0.f,0.f,0.f}};
    float oB[2][4] = {{0.f,0.f,0.f,0.f},{0.f,0.f,0.f,0.f}};
    for (int c0 = 0; c0 < Kdim; c0 += CK) {
        __syncthreads();
        // stage V chunk pre-packed: sV[pair p][d] = bf16x2{ V[2p][d], V[2p+1][d] }
#pragma unroll
        for (int i = 0; i < 8; i++) {
            int idx = tid + i * 256;      // 2048 steps: 32 pairs x 64 float2-cols
            int p  = idx >> 6;
            int c2 = idx & 63;
            const float* v0 = vp + (size_t)(c0 + 2 * p) * Dn + 2 * c2;
            float2 x0 = *(const float2*)v0;         // row 2p
            float2 x1 = *(const float2*)(v0 + Dn);  // row 2p+1
            uint32_t h0, l0, h1, l1;
            splitpack(x0.x, x1.x, h0, l0);          // col 2*c2
            splitpack(x0.y, x1.y, h1, l1);          // col 2*c2+1
            sVh[p * VPROW + 2 * c2]     = h0;
            sVh[p * VPROW + 2 * c2 + 1] = h1;
            sVl[p * VPROW + 2 * c2]     = l0;
            sVl[p * VPROW + 2 * c2 + 1] = l1;
        }
        __syncthreads();
#pragma unroll
        for (int kk = 0; kk < 4; kk++) {
            const float* Sb = sS + g * SROW + c0 + kk * 16 + 2 * ct;
            float2 x0 = *(const float2*)Sb;
            float2 x1 = *(const float2*)(Sb + 8 * SROW);
            float2 x2 = *(const float2*)(Sb + 8);
            float2 x3 = *(const float2*)(Sb + 8 * SROW + 8);
            uint32_t ah[4], al[4];
            splitpack(x0.x, x0.y, ah[0], al[0]);
            splitpack(x1.x, x1.y, ah[1], al[1]);
            splitpack(x2.x, x2.y, ah[2], al[2]);
            splitpack(x3.x, x3.y, ah[3], al[3]);
            int pr = kk * 8 + ct;                  // pair-row base
#pragma unroll
            for (int t = 0; t < 2; t++) {
                int d0 = (w * 2 + t) * 8 + g;
                uint32_t bh0 = sVh[pr * VPROW + d0];
                uint32_t bh1 = sVh[(pr + 4) * VPROW + d0];
                uint32_t bl0 = sVl[pr * VPROW + d0];
                uint32_t bl1 = sVl[(pr + 4) * VPROW + d0];
                MMA_BF16(oA[t], ah[0], ah[1], ah[2], ah[3], bh0, bh1);
                MMA_BF16(oB[t], ah[0], ah[1], ah[2], ah[3], bl0, bl1);
                MMA_BF16(oB[t], al[0], al[1], al[2], al[3], bh0, bh1);
            }
        }
    }

    float* op = outg + ((size_t)b * Qn + q0) * Dn;
#pragma unroll
    for (int t = 0; t < 2; t++) {
        int d0 = (w * 2 + t) * 8 + 2 * ct;
        op[g * Dn + d0]           = oA[t][0] + oB[t][0];
        op[g * Dn + d0 + 1]       = oA[t][1] + oB[t][1];
        op[(g + 8) * Dn + d0]     = oA[t][2] + oB[t][2];
        op[(g + 8) * Dn + d0 + 1] = oA[t][3] + oB[t][3];
    }
}

extern "C" void kernel_launch(void* const* d_in, const int* in_sizes, int n_in,
                              void* d_out, int out_size) {
    const float* q  = (const float*)d_in[0];
    const float* k  = (const float*)d_in[1];
    const float* v  = (const float*)d_in[2];
    const int*   vl = (const int*)d_in[3];
    float* out  = (float*)d_out;
    float* attn = out + (size_t)Bn * Qn * Dn;   // output tuple: (out, attn)

    cudaFuncSetAttribute(attn_fused_kernel,
                         cudaFuncAttributeMaxDynamicSharedMemorySize, SMEM_TOTAL);
    dim3 grid(Qn / QT, Bn);
    attn_fused_kernel<<<grid, 256, SMEM_TOTAL>>>(q, k, v, vl, out, attn);
}

// round 2
// speedup vs baseline: 1.7954x; 1.7954x over previous
#include <cuda_runtime.h>
#include <cuda_bf16.h>
#include <cstdint>

#define Bn 64
#define Qn 2048
#define Kn 2048
#define Dn 128

// ---------------- common helpers ----------------

#define MMA_BF16(C, a0, a1, a2, a3, b0, b1)                                   \
  asm volatile(                                                               \
      "mma.sync.aligned.m16n8k16.row.col.f32.bf16.bf16.f32 "                  \
      "{%0,%1,%2,%3}, {%4,%5,%6,%7}, {%8,%9}, {%0,%1,%2,%3};\n"               \
      : "+f"(C[0]), "+f"(C[1]), "+f"(C[2]), "+f"(C[3])                        \
      : "r"(a0), "r"(a1), "r"(a2), "r"(a3), "r"(b0), "r"(b1))

// Split two fp32 into (hi, lo) bf16x2 packs: x = hi + lo to ~2^-18 relative.
__device__ __forceinline__ void splitpack(float x, float y, uint32_t& h, uint32_t& l) {
    __nv_bfloat162 hh = __floats2bfloat162_rn(x, y);
    float hx = __low2float(hh);
    float hy = __high2float(hh);
    __nv_bfloat162 ll = __floats2bfloat162_rn(x - hx, y - hy);
    h = *reinterpret_cast<uint32_t*>(&hh);
    l = *reinterpret_cast<uint32_t*>(&ll);
}

__device__ __forceinline__ uint32_t smem_u32(const void* p) {
    return (uint32_t)__cvta_generic_to_shared(p);
}
__device__ __forceinline__ void cpasync16(uint32_t dst, const void* src) {
    asm volatile("cp.async.cg.shared.global [%0], [%1], 16;\n" :: "r"(dst), "l"(src));
}
#define CP_COMMIT asm volatile("cp.async.commit_group;\n" ::: "memory")
#define CP_WAIT0  asm volatile("cp.async.wait_group 0;\n" ::: "memory")

// ================= K1: raw scores GEMM =================
// S[b,i,j] = (1/sqrt(128)) * sum_d Q[b,i,d] K[b,j,d], written raw (unmasked)
// into the attn output buffer. CTA tile 128(M) x 128(N), K-dim = 128 (one pass).
// fp32 staged in smem via cp.async; bf16 hi/lo conversion at frag-load time.

#define QS 132   /* float stride for staged 128-col tiles (bank-friendly) */

__global__ void __launch_bounds__(256, 1)
scores_kernel(const float* __restrict__ qg, const float* __restrict__ kg,
              float* __restrict__ sg)
{
    extern __shared__ float sm1[];
    float* sQ = sm1;              // 128 x QS
    float* sK = sm1 + 128 * QS;   // 128 x QS

    const int b  = blockIdx.z;
    const int i0 = blockIdx.y * 128;
    const int j0 = blockIdx.x * 128;
    const int tid = threadIdx.x;
    const int w = tid >> 5, lane = tid & 31;
    const int g = lane >> 2, ct = lane & 3;
    const int wm = w >> 1;        // 0..3 -> m offset wm*32
    const int wn = w & 1;         // 0..1 -> n offset wn*64

    const float* qp = qg + ((size_t)b * Qn + i0) * Dn;
    const float* kp = kg + ((size_t)b * Kn + j0) * Dn;

#pragma unroll
    for (int it = 0; it < 16; it++) {
        int idx = tid + it * 256;          // 4096 float4 = 128 rows x 32
        int r = idx >> 5, c4 = (idx & 31) << 2;
        cpasync16(smem_u32(sQ + r * QS + c4), qp + (size_t)r * Dn + c4);
    }
#pragma unroll
    for (int it = 0; it < 16; it++) {
        int idx = tid + it * 256;
        int r = idx >> 5, c4 = (idx & 31) << 2;
        cpasync16(smem_u32(sK + r * QS + c4), kp + (size_t)r * Dn + c4);
    }
    CP_COMMIT; CP_WAIT0;
    __syncthreads();

    float acc[2][8][4] = {};
#pragma unroll
    for (int kk = 0; kk < 8; kk++) {
        uint32_t ah[2][4], al[2][4];
#pragma unroll
        for (int mf = 0; mf < 2; mf++) {
            const float* base = sQ + (wm * 32 + mf * 16) * QS + kk * 16 + 2 * ct;
            float2 x0 = *(const float2*)(base + g * QS);
            float2 x1 = *(const float2*)(base + (g + 8) * QS);
            float2 x2 = *(const float2*)(base + g * QS + 8);
            float2 x3 = *(const float2*)(base + (g + 8) * QS + 8);
            splitpack(x0.x, x0.y, ah[mf][0], al[mf][0]);
            splitpack(x1.x, x1.y, ah[mf][1], al[mf][1]);
            splitpack(x2.x, x2.y, ah[mf][2], al[mf][2]);
            splitpack(x3.x, x3.y, ah[mf][3], al[mf][3]);
        }
#pragma unroll
        for (int nf = 0; nf < 8; nf++) {
            const float* nb = sK + (wn * 64 + nf * 8 + g) * QS + kk * 16 + 2 * ct;
            float2 y0 = *(const float2*)nb;
            float2 y1 = *(const float2*)(nb + 8);
            uint32_t bh0, bl0, bh1, bl1;
            splitpack(y0.x, y0.y, bh0, bl0);
            splitpack(y1.x, y1.y, bh1, bl1);
#pragma unroll
            for (int mf = 0; mf < 2; mf++) {
                MMA_BF16(acc[mf][nf], ah[mf][0], ah[mf][1], ah[mf][2], ah[mf][3], bh0, bh1);
                MMA_BF16(acc[mf][nf], ah[mf][0], ah[mf][1], ah[mf][2], ah[mf][3], bl0, bl1);
                MMA_BF16(acc[mf][nf], al[mf][0], al[mf][1], al[mf][2], al[mf][3], bh0, bh1);
            }
        }
    }

    const float scale = 0.08838834764831845f;  // 1/sqrt(128)
#pragma unroll
    for (int mf = 0; mf < 2; mf++) {
#pragma unroll
        for (int nf = 0; nf < 8; nf++) {
            int row = i0 + wm * 32 + mf * 16 + g;
            int col = j0 + wn * 64 + nf * 8 + 2 * ct;
            float2 v0 = { acc[mf][nf][0] * scale, acc[mf][nf][1] * scale };
            float2 v1 = { acc[mf][nf][2] * scale, acc[mf][nf][3] * scale };
            *(float2*)(sg + ((size_t)b * Qn + row) * Kn + col)     = v0;
            *(float2*)(sg + ((size_t)b * Qn + row + 8) * Kn + col) = v1;
        }
    }
}

// ================= K2a: masked softmax in place =================
// One warp per row; whole row (2048 fp32) in registers. mask j>=VL -> 0;
// VL==0 -> uniform 1/2048 (matches jax: all -1e9 -> uniform).

__global__ void __launch_bounds__(256)
softmax_kernel(float* __restrict__ att, const int* __restrict__ vlg)
{
    const int b = blockIdx.y;
    const int row = blockIdx.x * 8 + (threadIdx.x >> 5);
    const int lane = threadIdx.x & 31;
    const int VL = vlg[b];
    float* rp = att + ((size_t)b * Qn + row) * Kn;

    if (VL == 0) {
        const float u = 1.0f / 2048.0f;
        float4 uu = { u, u, u, u };
#pragma unroll
        for (int it = 0; it < 16; it++)
            *(float4*)(rp + it * 128 + lane * 4) = uu;
        return;
    }

    float4 v[16];
#pragma unroll
    for (int it = 0; it < 16; it++)
        v[it] = *(const float4*)(rp + it * 128 + lane * 4);

    float m = -3.402823466e38f;
#pragma unroll
    for (int it = 0; it < 16; it++) {
        int j = it * 128 + lane * 4;
        if (j     < VL) m = fmaxf(m, v[it].x);
        if (j + 1 < VL) m = fmaxf(m, v[it].y);
        if (j + 2 < VL) m = fmaxf(m, v[it].z);
        if (j + 3 < VL) m = fmaxf(m, v[it].w);
    }
#pragma unroll
    for (int o = 16; o > 0; o >>= 1)
        m = fmaxf(m, __shfl_xor_sync(0xffffffffu, m, o));

    float s = 0.f;
#pragma unroll
    for (int it = 0; it < 16; it++) {
        int j = it * 128 + lane * 4;
        v[it].x = (j     < VL) ? __expf(v[it].x - m) : 0.f;
        v[it].y = (j + 1 < VL) ? __expf(v[it].y - m) : 0.f;
        v[it].z = (j + 2 < VL) ? __expf(v[it].z - m) : 0.f;
        v[it].w = (j + 3 < VL) ? __expf(v[it].w - m) : 0.f;
        s += v[it].x + v[it].y + v[it].z + v[it].w;
    }
#pragma unroll
    for (int o = 16; o > 0; o >>= 1)
        s += __shfl_xor_sync(0xffffffffu, s, o);
    float inv = 1.0f / s;

#pragma unroll
    for (int it = 0; it < 16; it++) {
        v[it].x *= inv; v[it].y *= inv; v[it].z *= inv; v[it].w *= inv;
        *(float4*)(rp + it * 128 + lane * 4) = v[it];
    }
}

// ================= K2b: out = attn x V =================
// CTA tile: M=128 rows x N=128 (full D), k-chunks of 64 over Kn=2048.
// fp32 staging via cp.async; bf16x3 split at frag-load time.

#define PR 68    /* float stride, P tile rows (k-contiguous) */
#define VR 132   /* float stride, V tile rows (n-contiguous) */

__global__ void __launch_bounds__(256)
pv_kernel(const float* __restrict__ att, const float* __restrict__ vg,
          float* __restrict__ outg)
{
    extern __shared__ float sm2[];
    float* sP = sm2;                 // 128 x PR
    float* sV = sm2 + 128 * PR;      // 64 x VR

    const int b  = blockIdx.y;
    const int i0 = blockIdx.x * 128;
    const int tid = threadIdx.x;
    const int w = tid >> 5, lane = tid & 31;
    const int g = lane >> 2, ct = lane & 3;
    const int wm = w >> 1;   // m offset wm*32
    const int wn = w & 1;    // n offset wn*64

    const float* pp = att + ((size_t)b * Qn + i0) * Kn;
    const float* vp = vg + (size_t)b * Kn * Dn;

    float acc[2][8][4] = {};

    for (int c0 = 0; c0 < Kn; c0 += 64) {
        __syncthreads();
#pragma unroll
        for (int it = 0; it < 8; it++) {          // P: 128 rows x 16 float4
            int idx = tid + it * 256;
            int r = idx >> 4, c4 = (idx & 15) << 2;
            cpasync16(smem_u32(sP + r * PR + c4), pp + (size_t)r * Kn + c0 + c4);
        }
#pragma unroll
        for (int it = 0; it < 8; it++) {          // V: 64 rows x 32 float4
            int idx = tid + it * 256;
            int r = idx >> 5, c4 = (idx & 31) << 2;
            cpasync16(smem_u32(sV + r * VR + c4), vp + (size_t)(c0 + r) * Dn + c4);
        }
        CP_COMMIT; CP_WAIT0;
        __syncthreads();

#pragma unroll
        for (int kk = 0; kk < 4; kk++) {
            uint32_t ah[2][4], al[2][4];
#pragma unroll
            for (int mf = 0; mf < 2; mf++) {
                const float* base = sP + (wm * 32 + mf * 16) * PR + kk * 16 + 2 * ct;
                float2 x0 = *(const float2*)(base + g * PR);
                float2 x1 = *(const float2*)(base + (g + 8) * PR);
                float2 x2 = *(const float2*)(base + g * PR + 8);
                float2 x3 = *(const float2*)(base + (g + 8) * PR + 8);
                splitpack(x0.x, x0.y, ah[mf][0], al[mf][0]);
                splitpack(x1.x, x1.y, ah[mf][1], al[mf][1]);
                splitpack(x2.x, x2.y, ah[mf][2], al[mf][2]);
                splitpack(x3.x, x3.y, ah[mf][3], al[mf][3]);
            }
#pragma unroll
            for (int nf = 0; nf < 8; nf++) {
                int n = wn * 64 + nf * 8 + g;
                const float* vb = sV + (kk * 16 + 2 * ct) * VR + n;
                float v00 = vb[0];
                float v01 = vb[VR];
                float v10 = vb[8 * VR];
                float v11 = vb[9 * VR];
                uint32_t bh0, bl0, bh1, bl1;
                splitpack(v00, v01, bh0, bl0);
                splitpack(v10, v11, bh1, bl1);
#pragma unroll
                for (int mf = 0; mf < 2; mf++) {
                    MMA_BF16(acc[mf][nf], ah[mf][0], ah[mf][1], ah[mf][2], ah[mf][3], bh0, bh1);
                    MMA_BF16(acc[mf][nf], ah[mf][0], ah[mf][1], ah[mf][2], ah[mf][3], bl0, bl1);
                    MMA_BF16(acc[mf][nf], al[mf][0], al[mf][1], al[mf][2], al[mf][3], bh0, bh1);
                }
            }
        }
    }

    float* op = outg + ((size_t)b * Qn + i0) * Dn;
#pragma unroll
    for (int mf = 0; mf < 2; mf++) {
#pragma unroll
        for (int nf = 0; nf < 8; nf++) {
            int row = wm * 32 + mf * 16 + g;
            int col = wn * 64 + nf * 8 + 2 * ct;
            float2 v0 = { acc[mf][nf][0], acc[mf][nf][1] };
            float2 v1 = { acc[mf][nf][2], acc[mf][nf][3] };
            *(float2*)(op + (size_t)row * Dn + col)       = v0;
            *(float2*)(op + (size_t)(row + 8) * Dn + col) = v1;
        }
    }
}

// ================= launch =================

extern "C" void kernel_launch(void* const* d_in, const int* in_sizes, int n_in,
                              void* d_out, int out_size) {
    const float* q  = (const float*)d_in[0];
    const float* k  = (const float*)d_in[1];
    const float* v  = (const float*)d_in[2];
    const int*   vl = (const int*)d_in[3];
    float* out  = (float*)d_out;
    float* attn = out + (size_t)Bn * Qn * Dn;   // output tuple: (out, attn)

    static int configured = 0;
    if (!configured) {
        cudaFuncSetAttribute(scores_kernel,
                             cudaFuncAttributeMaxDynamicSharedMemorySize, 2 * 128 * QS * 4);
        cudaFuncSetAttribute(pv_kernel,
                             cudaFuncAttributeMaxDynamicSharedMemorySize,
                             (128 * PR + 64 * VR) * 4);
        configured = 1;
    }

    dim3 g1(Kn / 128, Qn / 128, Bn);
    scores_kernel<<<g1, 256, 2 * 128 * QS * 4>>>(q, k, attn);

    dim3 g2(Qn / 8, Bn);
    softmax_kernel<<<g2, 256>>>(attn, vl);

    dim3 g3(Qn / 128, Bn);
    pv_kernel<<<g3, 256, (128 * PR + 64 * VR) * 4>>>(attn, v, out);
}